// round 6
// baseline (speedup 1.0000x reference)
#include <cuda_runtime.h>
#include <cuda_bf16.h>
#include <math.h>

// ---------------------------------------------------------------------------
// Attention_69226282877525: BERT-style MHA on sm_103a, tf32 mma.sync path.
//   B=2, F=T=2048, HIDDEN=1024, N_HEADS=16, HEAD_DIM=64
// Q/K scratch: [B][N][S][H] with h-columns interleaved within groups of 8
//   (col c stored at ((c&3)<<1)|(c>>2)) so mma (k,k+4) fragment pairs are
//   adjacent -> LDS.64 fragment loads.
// V scratch: TRANSPOSED [B][N][H][S] with the same interleave on t.
// ---------------------------------------------------------------------------

#define BATCH   2
#define SEQ     2048
#define HIDDEN  1024
#define NHEADS  16
#define HDIM    64
#define MROWS   (BATCH * SEQ)      // 4096

__device__ float g_Qs[(size_t)BATCH * NHEADS * SEQ * HDIM];
__device__ float g_Ks[(size_t)BATCH * NHEADS * SEQ * HDIM];
__device__ float g_Vs[(size_t)BATCH * NHEADS * SEQ * HDIM];
// Packed attention mask bits: [B][F][T/32]
__device__ unsigned g_Mbits[(size_t)BATCH * SEQ * (SEQ / 32)];

// --------------------------- helpers ---------------------------------------
__device__ __forceinline__ unsigned f2tf(float x) {
    unsigned r;
    asm("cvt.rna.tf32.f32 %0, %1;" : "=r"(r) : "f"(x));
    return r;
}
__device__ __forceinline__ float f2tf_f(float x) {
    return __uint_as_float(f2tf(x));
}
__device__ __forceinline__ void cvt4(float4& v) {
    v.x = f2tf_f(v.x); v.y = f2tf_f(v.y); v.z = f2tf_f(v.z); v.w = f2tf_f(v.w);
}
__device__ __forceinline__ void mma_tf32(float c[4], const unsigned a[4],
                                         const unsigned b[2]) {
    asm volatile(
        "mma.sync.aligned.m16n8k8.row.col.f32.tf32.tf32.f32 "
        "{%0,%1,%2,%3}, {%4,%5,%6,%7}, {%8,%9}, {%0,%1,%2,%3};\n"
        : "+f"(c[0]), "+f"(c[1]), "+f"(c[2]), "+f"(c[3])
        : "r"(a[0]), "r"(a[1]), "r"(a[2]), "r"(a[3]), "r"(b[0]), "r"(b[1]));
}
__device__ __forceinline__ void cp_async16(float* dst_smem, const float* src) {
    unsigned d = (unsigned)__cvta_generic_to_shared(dst_smem);
    asm volatile("cp.async.cg.shared.global [%0], [%1], 16;" :: "r"(d), "l"(src));
}
__device__ __forceinline__ void cp_commit() {
    asm volatile("cp.async.commit_group;");
}
template<int N> __device__ __forceinline__ void cp_wait() {
    asm volatile("cp.async.wait_group %0;" :: "n"(N));
}

// ---------------------------------------------------------------------------
// Pack mask [B,F,T] int32 -> bitmask [B,F,T/32]. One warp per (b,f) row.
// ---------------------------------------------------------------------------
__global__ __launch_bounds__(256) void mask_bits_kernel(
    const int* __restrict__ mask, unsigned* __restrict__ bits)
{
    const int gw   = (blockIdx.x * 256 + threadIdx.x) >> 5;
    const int lane = threadIdx.x & 31;
    if (gw >= BATCH * SEQ) return;
    const int* mp = mask + (size_t)gw * SEQ;
    unsigned* bp  = bits + (size_t)gw * (SEQ / 32);
    #pragma unroll 4
    for (int c = 0; c < SEQ / 32; c++) {
        const int v = mp[c * 32 + lane];
        const unsigned w = __ballot_sync(0xffffffffu, v != 0);
        if (lane == 0) bp[c] = w;
    }
}

// ---------------------------------------------------------------------------
// Merged QKV projection GEMM (tf32 mma.sync): blockIdx.z in {Q,K,V}.
// Q/K epilogue: interleaved h columns. V epilogue: transposed + interleaved t.
// ---------------------------------------------------------------------------
#define GA_STR 20
#define GB_STR 136
#define GEMM_SMEM ((2 * 128 * GA_STR + 2 * 16 * GB_STR) * 4)   // 37888 bytes

__global__ __launch_bounds__(256, 2) void gemm_mma_kernel(
    const float* __restrict__ Xq, const float* __restrict__ Xkv,
    const float* __restrict__ Wq, const float* __restrict__ bq,
    const float* __restrict__ Wk, const float* __restrict__ bk,
    const float* __restrict__ Wv, const float* __restrict__ bv,
    float* __restrict__ oq, float* __restrict__ ok, float* __restrict__ ov)
{
    extern __shared__ float smg[];
    float* As = smg;
    float* Bs = smg + 2 * 128 * GA_STR;

    const float* X; const float* W; const float* bias; float* out;
    if (blockIdx.z == 0)      { X = Xq;  W = Wq; bias = bq; out = oq; }
    else if (blockIdx.z == 1) { X = Xkv; W = Wk; bias = bk; out = ok; }
    else                      { X = Xkv; W = Wv; bias = bv; out = ov; }
    const bool vtrans = (blockIdx.z == 2);

    const int tid  = threadIdx.x;
    const int w    = tid >> 5;
    const int lane = tid & 31;
    const int gid  = lane >> 2;
    const int tid4 = lane & 3;
    const int wm   = w & 3;
    const int wn   = w >> 2;
    const int row0 = blockIdx.y * 128;
    const int col0 = blockIdx.x * 128;

    float4 ar[2], br[2];

    #pragma unroll
    for (int i = 0; i < 2; i++) {
        const int idx = tid + i * 256;
        { const int r = idx >> 2, c4 = idx & 3;
          ar[i] = *(const float4*)(X + (size_t)(row0 + r) * HIDDEN + c4 * 4); }
        { const int r = idx >> 5, c4 = idx & 31;
          br[i] = *(const float4*)(W + (size_t)r * HIDDEN + col0 + c4 * 4); }
    }
    #pragma unroll
    for (int i = 0; i < 2; i++) {
        const int idx = tid + i * 256;
        cvt4(ar[i]); cvt4(br[i]);
        { const int r = idx >> 2, c4 = idx & 3;
          *(float4*)(As + r * GA_STR + c4 * 4) = ar[i]; }
        { const int r = idx >> 5, c4 = idx & 31;
          *(float4*)(Bs + r * GB_STR + c4 * 4) = br[i]; }
    }
    __syncthreads();

    float C[2][8][4] = {};

    for (int kt = 0; kt < 64; kt++) {
        const int buf = kt & 1;
        if (kt < 63) {
            const int k0 = (kt + 1) * 16;
            #pragma unroll
            for (int i = 0; i < 2; i++) {
                const int idx = tid + i * 256;
                { const int r = idx >> 2, c4 = idx & 3;
                  ar[i] = *(const float4*)(X + (size_t)(row0 + r) * HIDDEN + k0 + c4 * 4); }
                { const int r = idx >> 5, c4 = idx & 31;
                  br[i] = *(const float4*)(W + (size_t)(k0 + r) * HIDDEN + col0 + c4 * 4); }
            }
        }
        const float* Ab = As + buf * 128 * GA_STR;
        const float* Bb = Bs + buf * 16 * GB_STR;
        #pragma unroll
        for (int ks = 0; ks < 2; ks++) {
            unsigned a[2][4];
            #pragma unroll
            for (int mb = 0; mb < 2; mb++) {
                const int base = (wm * 32 + mb * 16 + gid) * GA_STR + ks * 8 + tid4;
                a[mb][0] = __float_as_uint(Ab[base]);
                a[mb][1] = __float_as_uint(Ab[base + 8 * GA_STR]);
                a[mb][2] = __float_as_uint(Ab[base + 4]);
                a[mb][3] = __float_as_uint(Ab[base + 8 * GA_STR + 4]);
            }
            #pragma unroll
            for (int nb = 0; nb < 8; nb++) {
                unsigned bf[2];
                const int bbase = (ks * 8 + tid4) * GB_STR + wn * 64 + nb * 8 + gid;
                bf[0] = __float_as_uint(Bb[bbase]);
                bf[1] = __float_as_uint(Bb[bbase + 4 * GB_STR]);
                mma_tf32(C[0][nb], a[0], bf);
                mma_tf32(C[1][nb], a[1], bf);
            }
        }
        if (kt < 63) {
            float* An = As + ((kt + 1) & 1) * 128 * GA_STR;
            float* Bn = Bs + ((kt + 1) & 1) * 16 * GB_STR;
            #pragma unroll
            for (int i = 0; i < 2; i++) {
                const int idx = tid + i * 256;
                cvt4(ar[i]); cvt4(br[i]);
                { const int r = idx >> 2, c4 = idx & 3;
                  *(float4*)(An + r * GA_STR + c4 * 4) = ar[i]; }
                { const int r = idx >> 5, c4 = idx & 31;
                  *(float4*)(Bn + r * GB_STR + c4 * 4) = br[i]; }
            }
        }
        __syncthreads();
    }

    // epilogue: bias + tf32 round + interleaved store
    const int colbase = col0 + wn * 64;       // multiple of 64
    const int nhead   = colbase >> 6;
    // interleave position of actual col w within its 8-group: ((w&3)<<1)|(w>>2)
    const int pos0 = ((tid4 & 1) << 2) | (tid4 >> 1);   // for w = 2*tid4
    const int pos1 = pos0 + 2;                          // for w = 2*tid4+1
    #pragma unroll
    for (int mb = 0; mb < 2; mb++) {
        #pragma unroll
        for (int h = 0; h < 2; h++) {
            const int row = row0 + wm * 32 + mb * 16 + gid + 8 * h;
            const int b   = row >> 11;
            const int s   = row & 2047;
            if (!vtrans) {
                float* op = out + (((size_t)b * NHEADS + nhead) * SEQ + s) * HDIM;
                #pragma unroll
                for (int nb = 0; nb < 8; nb++) {
                    const int hh = nb * 8 + 2 * tid4;
                    op[nb * 8 + pos0] = f2tf_f(C[mb][nb][2 * h]     + bias[colbase + hh]);
                    op[nb * 8 + pos1] = f2tf_f(C[mb][nb][2 * h + 1] + bias[colbase + hh + 1]);
                }
            } else {
                // V: [B][N][H][S], t = s interleaved within 8-groups
                const int sp = (s & ~7) | (((s & 3) << 1) | ((s & 4) >> 2));
                float* op = out + ((size_t)b * NHEADS + nhead) * HDIM * SEQ + sp;
                #pragma unroll
                for (int nb = 0; nb < 8; nb++) {
                    const int hh = nb * 8 + 2 * tid4;
                    op[(size_t)hh * SEQ] =
                        f2tf_f(C[mb][nb][2 * h] + bias[colbase + hh]);
                    op[(size_t)(hh + 1) * SEQ] =
                        f2tf_f(C[mb][nb][2 * h + 1] + bias[colbase + hh + 1]);
                }
            }
        }
    }
}

// ---------------------------------------------------------------------------
// Flash attention (tf32 mma.sync): CTA 128 thr (4 warps x 32 rows),
// f-tile 128, T-tile 64. All fragment loads are LDS.64 (interleaved layout).
// No-max softmax: p = bit ? exp(0.125*s) : 0; O accumulates unrescaled;
// row sums reduced once at the epilogue.
// ---------------------------------------------------------------------------
#define FQ_STR 68
#define FK_STR 68
#define FV_STR 68
#define ATT_SMEM ((128 * FQ_STR + 64 * FK_STR + 64 * FV_STR) * 4)  // 69632

__global__ __launch_bounds__(128, 3) void flash_mma_kernel(
    const float* __restrict__ Q, const float* __restrict__ K,
    const float* __restrict__ Vt, const unsigned* __restrict__ mbitsg,
    float* __restrict__ out)
{
    extern __shared__ float sm[];
    float* Qs = sm;                       // [128][68]
    float* Ks = Qs + 128 * FQ_STR;        // [64][68]
    float* Vs = Ks + 64 * FK_STR;         // [64][68]  (V^T tile: rows=h, cols=t)

    const int tid  = threadIdx.x;
    const int w    = tid >> 5;
    const int lane = tid & 31;
    const int gid  = lane >> 2;
    const int tid4 = lane & 3;

    const int bn = blockIdx.y;            // b*16 + head
    const int b  = bn >> 4;
    const int nh = bn & 15;
    const int f0 = blockIdx.x * 128;

    const float* Qp = Q + ((size_t)bn * SEQ + f0) * HDIM;
    const float* Kp = K + (size_t)bn * SEQ * HDIM;
    const float* Vp = Vt + (size_t)bn * HDIM * SEQ;   // [H][S]
    const unsigned* Mb = mbitsg + (size_t)b * SEQ * (SEQ / 32);

    // prologue: stage Q + K0 (group A), V0 (group B)
    #pragma unroll
    for (int i = 0; i < 16; i++) {
        const int idx = tid + i * 128;
        const int r = idx >> 4, c = idx & 15;
        cp_async16(Qs + r * FQ_STR + c * 4, Qp + (size_t)r * HDIM + c * 4);
    }
    #pragma unroll
    for (int i = 0; i < 8; i++) {
        const int idx = tid + i * 128;
        const int r = idx >> 4, c = idx & 15;
        cp_async16(Ks + r * FK_STR + c * 4, Kp + (size_t)r * HDIM + c * 4);
    }
    cp_commit();
    #pragma unroll
    for (int i = 0; i < 8; i++) {
        const int idx = tid + i * 128;
        const int r = idx >> 4, c = idx & 15;   // r = h row, c = t chunk
        cp_async16(Vs + r * FV_STR + c * 4, Vp + (size_t)r * SEQ + c * 4);
    }
    cp_commit();

    float O[2][8][4] = {};
    float lrow[2][2] = {};

    for (int t0 = 0; t0 < SEQ; t0 += 64) {
        cp_wait<1>();          // K(t) ready (V(t) may still be in flight)
        __syncthreads();

        // prefetch mask bits for this tile (hidden behind QK mma)
        unsigned long long mbits[2][2];
        #pragma unroll
        for (int mb = 0; mb < 2; mb++)
            #pragma unroll
            for (int h = 0; h < 2; h++) {
                const int rg = f0 + w * 32 + mb * 16 + gid + 8 * h;
                const uint2 mm = *(const uint2*)(Mb + (size_t)rg * (SEQ / 32) + (t0 >> 5));
                mbits[mb][h] = (unsigned long long)mm.x |
                               ((unsigned long long)mm.y << 32);
            }

        // ---- S = Q @ K^T (all fragment pairs via LDS.64) ----
        float S[2][8][4] = {};
        #pragma unroll
        for (int ks = 0; ks < 8; ks++) {
            unsigned a[2][4];
            #pragma unroll
            for (int mb = 0; mb < 2; mb++) {
                const int base = (w * 32 + mb * 16 + gid) * FQ_STR + ks * 8 + 2 * tid4;
                const float2 p0 = *(const float2*)(Qs + base);
                const float2 p1 = *(const float2*)(Qs + base + 8 * FQ_STR);
                a[mb][0] = __float_as_uint(p0.x);
                a[mb][2] = __float_as_uint(p0.y);
                a[mb][1] = __float_as_uint(p1.x);
                a[mb][3] = __float_as_uint(p1.y);
            }
            #pragma unroll
            for (int nb = 0; nb < 8; nb++) {
                const float2 bb = *(const float2*)(Ks + (nb * 8 + gid) * FK_STR + ks * 8 + 2 * tid4);
                unsigned bf[2];
                bf[0] = __float_as_uint(bb.x);
                bf[1] = __float_as_uint(bb.y);
                mma_tf32(S[0][nb], a[0], bf);
                mma_tf32(S[1][nb], a[1], bf);
            }
        }
        __syncthreads();       // all warps done reading K tile

        // prefetch next K tile (overlaps softmax + PV)
        if (t0 + 64 < SEQ) {
            #pragma unroll
            for (int i = 0; i < 8; i++) {
                const int idx = tid + i * 128;
                const int r = idx >> 4, c = idx & 15;
                cp_async16(Ks + r * FK_STR + c * 4,
                           Kp + (size_t)(t0 + 64 + r) * HDIM + c * 4);
            }
            cp_commit();
        }

        // ---- no-max softmax: p = bit ? exp(0.125*s) : 0 ----
        #pragma unroll
        for (int mb = 0; mb < 2; mb++) {
            #pragma unroll
            for (int h = 0; h < 2; h++) {
                const unsigned long long m64 = mbits[mb][h];
                float ls = 0.0f;
                #pragma unroll
                for (int nb = 0; nb < 8; nb++) {
                    const int pos = nb * 8 + 2 * tid4;
                    const float p0 = ((m64 >> pos) & 1ULL)
                                   ? __expf(0.125f * S[mb][nb][2 * h]) : 0.0f;
                    const float p1 = ((m64 >> (pos + 1)) & 1ULL)
                                   ? __expf(0.125f * S[mb][nb][2 * h + 1]) : 0.0f;
                    ls += p0 + p1;
                    S[mb][nb][2 * h]     = p0;
                    S[mb][nb][2 * h + 1] = p1;
                }
                lrow[mb][h] += ls;
            }
        }

        // wait for V(t); pending afterwards: only K(t+1) (if any)
        if (t0 + 64 < SEQ) cp_wait<1>(); else cp_wait<0>();
        __syncthreads();

        // ---- O += P @ V : shuffle-transpose P C-frag -> A-frag ----
        const int src0 = (lane & 28) | (tid4 >> 1);
        const int src1 = src0 + 2;
        const bool odd = (tid4 & 1);
        #pragma unroll
        for (int kt = 0; kt < 8; kt++) {
            unsigned a[2][4];
            #pragma unroll
            for (int mb = 0; mb < 2; mb++) {
                float e0 = __shfl_sync(0xffffffffu, S[mb][kt][0], src0);
                float o0 = __shfl_sync(0xffffffffu, S[mb][kt][1], src0);
                float e1 = __shfl_sync(0xffffffffu, S[mb][kt][0], src1);
                float o1 = __shfl_sync(0xffffffffu, S[mb][kt][1], src1);
                float e2 = __shfl_sync(0xffffffffu, S[mb][kt][2], src0);
                float o2 = __shfl_sync(0xffffffffu, S[mb][kt][3], src0);
                float e3 = __shfl_sync(0xffffffffu, S[mb][kt][2], src1);
                float o3 = __shfl_sync(0xffffffffu, S[mb][kt][3], src1);
                a[mb][0] = f2tf(odd ? o0 : e0);
                a[mb][1] = f2tf(odd ? o2 : e2);
                a[mb][2] = f2tf(odd ? o1 : e1);
                a[mb][3] = f2tf(odd ? o3 : e3);
            }
            #pragma unroll
            for (int nb = 0; nb < 8; nb++) {
                // V^T tile: row = h (nb*8+gid), col pair = t (kt*8 + {tid4, tid4+4})
                const float2 vv = *(const float2*)(Vs + (nb * 8 + gid) * FV_STR + kt * 8 + 2 * tid4);
                unsigned bf[2];
                bf[0] = __float_as_uint(vv.x);
                bf[1] = __float_as_uint(vv.y);
                mma_tf32(O[0][nb], a[0], bf);
                mma_tf32(O[1][nb], a[1], bf);
            }
        }
        __syncthreads();       // all warps done reading V tile

        // prefetch next V tile (overlaps next QK)
        if (t0 + 64 < SEQ) {
            #pragma unroll
            for (int i = 0; i < 8; i++) {
                const int idx = tid + i * 128;
                const int r = idx >> 4, c = idx & 15;
                cp_async16(Vs + r * FV_STR + c * 4,
                           Vp + (size_t)r * SEQ + t0 + 64 + c * 4);
            }
            cp_commit();
        }
    }

    // ---- epilogue: reduce row sums (once), normalize, store ----
    #pragma unroll
    for (int mb = 0; mb < 2; mb++) {
        #pragma unroll
        for (int h = 0; h < 2; h++) {
            float l = lrow[mb][h];
            l += __shfl_xor_sync(0xffffffffu, l, 1);
            l += __shfl_xor_sync(0xffffffffu, l, 2);
            const float linv = 1.0f / l;
            const int rg = f0 + w * 32 + mb * 16 + gid + 8 * h;
            float* op = out + ((size_t)b * SEQ + rg) * HIDDEN + nh * HDIM;
            #pragma unroll
            for (int nb = 0; nb < 8; nb++) {
                float2 v;
                v.x = O[mb][nb][2 * h] * linv;
                v.y = O[mb][nb][2 * h + 1] * linv;
                *(float2*)(op + nb * 8 + 2 * tid4) = v;
            }
        }
    }
}

// ---------------------------------------------------------------------------
// kernel_launch
// ---------------------------------------------------------------------------
extern "C" void kernel_launch(void* const* d_in, const int* in_sizes, int n_in,
                              void* d_out, int out_size)
{
    (void)in_sizes; (void)n_in; (void)out_size;

    const float* from_t = (const float*)d_in[0];
    const float* to_t   = (const float*)d_in[1];
    const int*   msk    = (const int*)d_in[2];
    const float* Wq     = (const float*)d_in[3];
    const float* bq     = (const float*)d_in[4];
    const float* Wk     = (const float*)d_in[5];
    const float* bk     = (const float*)d_in[6];
    const float* Wv     = (const float*)d_in[7];
    const float* bv     = (const float*)d_in[8];
    float* out = (float*)d_out;

    float *qp, *kp, *vp; unsigned* mb;
    cudaGetSymbolAddress((void**)&qp, g_Qs);
    cudaGetSymbolAddress((void**)&kp, g_Ks);
    cudaGetSymbolAddress((void**)&vp, g_Vs);
    cudaGetSymbolAddress((void**)&mb, g_Mbits);

    cudaFuncSetAttribute(gemm_mma_kernel,
                         cudaFuncAttributeMaxDynamicSharedMemorySize, GEMM_SMEM);
    cudaFuncSetAttribute(flash_mma_kernel,
                         cudaFuncAttributeMaxDynamicSharedMemorySize, ATT_SMEM);

    // pack mask to bits (independent of GEMM outputs)
    mask_bits_kernel<<<(MROWS * 32 + 255) / 256, 256>>>(msk, mb);

    dim3 gg(HIDDEN / 128, MROWS / 128, 3);   // (8, 32, 3)
    gemm_mma_kernel<<<gg, 256, GEMM_SMEM>>>(from_t, to_t, Wq, bq, Wk, bk,
                                            Wv, bv, qp, kp, vp);

    dim3 gf(SEQ / 128, BATCH * NHEADS);      // (16, 32)
    flash_mma_kernel<<<gf, 128, ATT_SMEM>>>(qp, kp, vp, mb, out);
}

// round 7
// speedup vs baseline: 1.1346x; 1.1346x over previous
#include <cuda_runtime.h>
#include <cuda_bf16.h>
#include <math.h>

// ---------------------------------------------------------------------------
// Attention_69226282877525: BERT-style MHA on sm_103a, tf32 mma.sync path.
//   B=2, F=T=2048, HIDDEN=1024, N_HEADS=16, HEAD_DIM=64
// R7 = R4 structure (proven 527us) + no-max softmax (scores bounded, masked
// entries exact-0 in both ours and reference).
// ---------------------------------------------------------------------------

#define BATCH   2
#define SEQ     2048
#define HIDDEN  1024
#define NHEADS  16
#define HDIM    64
#define MROWS   (BATCH * SEQ)      // 4096

// Scratch for Q/K/V in [B][N][S][H] layout, tf32-pre-rounded fp32 (16 MB each)
__device__ float g_Qs[(size_t)BATCH * NHEADS * SEQ * HDIM];
__device__ float g_Ks[(size_t)BATCH * NHEADS * SEQ * HDIM];
__device__ float g_Vs[(size_t)BATCH * NHEADS * SEQ * HDIM];
// Packed attention mask bits: [B][F][T/32] (1 MB)
__device__ unsigned g_Mbits[(size_t)BATCH * SEQ * (SEQ / 32)];

// --------------------------- helpers ---------------------------------------
__device__ __forceinline__ unsigned f2tf(float x) {
    unsigned r;
    asm("cvt.rna.tf32.f32 %0, %1;" : "=r"(r) : "f"(x));
    return r;
}
__device__ __forceinline__ float f2tf_f(float x) {
    return __uint_as_float(f2tf(x));
}
__device__ __forceinline__ void cvt4(float4& v) {
    v.x = f2tf_f(v.x); v.y = f2tf_f(v.y); v.z = f2tf_f(v.z); v.w = f2tf_f(v.w);
}
__device__ __forceinline__ void mma_tf32(float c[4], const unsigned a[4],
                                         const unsigned b[2]) {
    asm volatile(
        "mma.sync.aligned.m16n8k8.row.col.f32.tf32.tf32.f32 "
        "{%0,%1,%2,%3}, {%4,%5,%6,%7}, {%8,%9}, {%0,%1,%2,%3};\n"
        : "+f"(c[0]), "+f"(c[1]), "+f"(c[2]), "+f"(c[3])
        : "r"(a[0]), "r"(a[1]), "r"(a[2]), "r"(a[3]), "r"(b[0]), "r"(b[1]));
}
__device__ __forceinline__ void cp_async16(float* dst_smem, const float* src) {
    unsigned d = (unsigned)__cvta_generic_to_shared(dst_smem);
    asm volatile("cp.async.cg.shared.global [%0], [%1], 16;" :: "r"(d), "l"(src));
}
__device__ __forceinline__ void cp_commit() {
    asm volatile("cp.async.commit_group;");
}
template<int N> __device__ __forceinline__ void cp_wait() {
    asm volatile("cp.async.wait_group %0;" :: "n"(N));
}

// ---------------------------------------------------------------------------
// Pack mask [B,F,T] int32 -> bitmask [B,F,T/32]. One warp per (b,f) row.
// ---------------------------------------------------------------------------
__global__ __launch_bounds__(256) void mask_bits_kernel(
    const int* __restrict__ mask, unsigned* __restrict__ bits)
{
    const int gw   = (blockIdx.x * 256 + threadIdx.x) >> 5;   // row index
    const int lane = threadIdx.x & 31;
    if (gw >= BATCH * SEQ) return;
    const int* mp = mask + (size_t)gw * SEQ;
    unsigned* bp  = bits + (size_t)gw * (SEQ / 32);
    #pragma unroll 4
    for (int c = 0; c < SEQ / 32; c++) {
        const int v = mp[c * 32 + lane];
        const unsigned w = __ballot_sync(0xffffffffu, v != 0);
        if (lane == 0) bp[c] = w;
    }
}

// ---------------------------------------------------------------------------
// Merged QKV projection GEMM (tf32 mma): blockIdx.z in {Q,K,V}.
// CTA 256 thr, tile 128x128, ktile 16, 8 warps (4m x 2n), warp tile 32x64.
// ---------------------------------------------------------------------------
#define GA_STR 20
#define GB_STR 136
#define GEMM_SMEM ((2 * 128 * GA_STR + 2 * 16 * GB_STR) * 4)   // 37888 bytes

__global__ __launch_bounds__(256, 2) void gemm_mma_kernel(
    const float* __restrict__ Xq, const float* __restrict__ Xkv,
    const float* __restrict__ Wq, const float* __restrict__ bq,
    const float* __restrict__ Wk, const float* __restrict__ bk,
    const float* __restrict__ Wv, const float* __restrict__ bv,
    float* __restrict__ oq, float* __restrict__ ok, float* __restrict__ ov)
{
    extern __shared__ float smg[];
    float* As = smg;                       // [2][128][GA_STR]
    float* Bs = smg + 2 * 128 * GA_STR;    // [2][16][GB_STR]

    const float* X; const float* W; const float* bias; float* out;
    if (blockIdx.z == 0)      { X = Xq;  W = Wq; bias = bq; out = oq; }
    else if (blockIdx.z == 1) { X = Xkv; W = Wk; bias = bk; out = ok; }
    else                      { X = Xkv; W = Wv; bias = bv; out = ov; }

    const int tid  = threadIdx.x;
    const int w    = tid >> 5;
    const int lane = tid & 31;
    const int gid  = lane >> 2;
    const int tid4 = lane & 3;
    const int wm   = w & 3;
    const int wn   = w >> 2;
    const int row0 = blockIdx.y * 128;
    const int col0 = blockIdx.x * 128;

    float4 ar[2], br[2];

    #pragma unroll
    for (int i = 0; i < 2; i++) {
        const int idx = tid + i * 256;
        { const int r = idx >> 2, c4 = idx & 3;
          ar[i] = *(const float4*)(X + (size_t)(row0 + r) * HIDDEN + c4 * 4); }
        { const int r = idx >> 5, c4 = idx & 31;
          br[i] = *(const float4*)(W + (size_t)r * HIDDEN + col0 + c4 * 4); }
    }
    #pragma unroll
    for (int i = 0; i < 2; i++) {
        const int idx = tid + i * 256;
        cvt4(ar[i]); cvt4(br[i]);
        { const int r = idx >> 2, c4 = idx & 3;
          *(float4*)(As + r * GA_STR + c4 * 4) = ar[i]; }
        { const int r = idx >> 5, c4 = idx & 31;
          *(float4*)(Bs + r * GB_STR + c4 * 4) = br[i]; }
    }
    __syncthreads();

    float C[2][8][4] = {};

    for (int kt = 0; kt < 64; kt++) {
        const int buf = kt & 1;
        if (kt < 63) {
            const int k0 = (kt + 1) * 16;
            #pragma unroll
            for (int i = 0; i < 2; i++) {
                const int idx = tid + i * 256;
                { const int r = idx >> 2, c4 = idx & 3;
                  ar[i] = *(const float4*)(X + (size_t)(row0 + r) * HIDDEN + k0 + c4 * 4); }
                { const int r = idx >> 5, c4 = idx & 31;
                  br[i] = *(const float4*)(W + (size_t)(k0 + r) * HIDDEN + col0 + c4 * 4); }
            }
        }
        const float* Ab = As + buf * 128 * GA_STR;
        const float* Bb = Bs + buf * 16 * GB_STR;
        #pragma unroll
        for (int ks = 0; ks < 2; ks++) {
            unsigned a[2][4];
            #pragma unroll
            for (int mb = 0; mb < 2; mb++) {
                const int base = (wm * 32 + mb * 16 + gid) * GA_STR + ks * 8 + tid4;
                a[mb][0] = __float_as_uint(Ab[base]);
                a[mb][1] = __float_as_uint(Ab[base + 8 * GA_STR]);
                a[mb][2] = __float_as_uint(Ab[base + 4]);
                a[mb][3] = __float_as_uint(Ab[base + 8 * GA_STR + 4]);
            }
            #pragma unroll
            for (int nb = 0; nb < 8; nb++) {
                unsigned bf[2];
                const int bbase = (ks * 8 + tid4) * GB_STR + wn * 64 + nb * 8 + gid;
                bf[0] = __float_as_uint(Bb[bbase]);
                bf[1] = __float_as_uint(Bb[bbase + 4 * GB_STR]);
                mma_tf32(C[0][nb], a[0], bf);
                mma_tf32(C[1][nb], a[1], bf);
            }
        }
        if (kt < 63) {
            float* An = As + ((kt + 1) & 1) * 128 * GA_STR;
            float* Bn = Bs + ((kt + 1) & 1) * 16 * GB_STR;
            #pragma unroll
            for (int i = 0; i < 2; i++) {
                const int idx = tid + i * 256;
                cvt4(ar[i]); cvt4(br[i]);
                { const int r = idx >> 2, c4 = idx & 3;
                  *(float4*)(An + r * GA_STR + c4 * 4) = ar[i]; }
                { const int r = idx >> 5, c4 = idx & 31;
                  *(float4*)(Bn + r * GB_STR + c4 * 4) = br[i]; }
            }
        }
        __syncthreads();
    }

    // epilogue: bias + tf32 round + transpose-store to [B][N][S][H]
    const int colbase = col0 + wn * 64;
    const int nhead   = colbase >> 6;
    #pragma unroll
    for (int mb = 0; mb < 2; mb++) {
        #pragma unroll
        for (int h = 0; h < 2; h++) {
            const int row = row0 + wm * 32 + mb * 16 + gid + 8 * h;
            const int b   = row >> 11;
            const int s   = row & 2047;
            float* op = out + (((size_t)b * NHEADS + nhead) * SEQ + s) * HDIM;
            #pragma unroll
            for (int nb = 0; nb < 8; nb++) {
                const int hh = nb * 8 + 2 * tid4;
                float2 v;
                v.x = f2tf_f(C[mb][nb][2 * h]     + bias[colbase + hh]);
                v.y = f2tf_f(C[mb][nb][2 * h + 1] + bias[colbase + hh + 1]);
                *(float2*)(op + hh) = v;
            }
        }
    }
}

// ---------------------------------------------------------------------------
// Flash attention (tf32 mma): CTA 128 thr (4 warps x 32 rows), f-tile 128,
// T-tile 64. Q/K/V pre-rounded tf32 via cp.async; split K/V wait groups;
// mask via packed bits. No-max softmax: p = bit ? exp(s/8) : 0;
// O never rescaled; row sums reduced once in the epilogue.
// ---------------------------------------------------------------------------
#define FQ_STR 68
#define FK_STR 68
#define FV_STR 72
#define ATT_SMEM ((128 * FQ_STR + 64 * FK_STR + 64 * FV_STR) * 4)  // 70656

__global__ __launch_bounds__(128, 3) void flash_mma_kernel(
    const float* __restrict__ Q, const float* __restrict__ K,
    const float* __restrict__ V, const unsigned* __restrict__ mbitsg,
    float* __restrict__ out)
{
    extern __shared__ float sm[];
    float* Qs = sm;                       // [128][68]
    float* Ks = Qs + 128 * FQ_STR;        // [64][68]
    float* Vs = Ks + 64 * FK_STR;         // [64][72]

    const int tid  = threadIdx.x;
    const int w    = tid >> 5;
    const int lane = tid & 31;
    const int gid  = lane >> 2;
    const int tid4 = lane & 3;

    const int bn = blockIdx.y;            // b*16 + head
    const int b  = bn >> 4;
    const int nh = bn & 15;
    const int f0 = blockIdx.x * 128;

    const float* Qp = Q + ((size_t)bn * SEQ + f0) * HDIM;
    const float* Kp = K + (size_t)bn * SEQ * HDIM;
    const float* Vp = V + (size_t)bn * SEQ * HDIM;
    const unsigned* Mb = mbitsg + (size_t)b * SEQ * (SEQ / 32);

    // prologue: stage Q + K0 (group A), V0 (group B)
    #pragma unroll
    for (int i = 0; i < 16; i++) {
        const int idx = tid + i * 128;
        const int r = idx >> 4, c = idx & 15;
        cp_async16(Qs + r * FQ_STR + c * 4, Qp + (size_t)r * HDIM + c * 4);
    }
    #pragma unroll
    for (int i = 0; i < 8; i++) {
        const int idx = tid + i * 128;
        const int r = idx >> 4, c = idx & 15;
        cp_async16(Ks + r * FK_STR + c * 4, Kp + (size_t)r * HDIM + c * 4);
    }
    cp_commit();
    #pragma unroll
    for (int i = 0; i < 8; i++) {
        const int idx = tid + i * 128;
        const int r = idx >> 4, c = idx & 15;
        cp_async16(Vs + r * FV_STR + c * 4, Vp + (size_t)r * HDIM + c * 4);
    }
    cp_commit();

    float O[2][8][4] = {};
    float lrow[2][2] = {};

    for (int t0 = 0; t0 < SEQ; t0 += 64) {
        cp_wait<1>();          // K(t) ready (V(t) may still be in flight)
        __syncthreads();

        // prefetch mask bits for this tile (hidden behind QK mma)
        unsigned long long mbits[2][2];
        #pragma unroll
        for (int mb = 0; mb < 2; mb++)
            #pragma unroll
            for (int h = 0; h < 2; h++) {
                const int rg = f0 + w * 32 + mb * 16 + gid + 8 * h;
                const uint2 mm = *(const uint2*)(Mb + (size_t)rg * (SEQ / 32) + (t0 >> 5));
                mbits[mb][h] = (unsigned long long)mm.x |
                               ((unsigned long long)mm.y << 32);
            }

        // ---- S = Q @ K^T ----
        float S[2][8][4] = {};
        #pragma unroll
        for (int ks = 0; ks < 8; ks++) {
            unsigned a[2][4];
            #pragma unroll
            for (int mb = 0; mb < 2; mb++) {
                const int base = (w * 32 + mb * 16 + gid) * FQ_STR + ks * 8 + tid4;
                a[mb][0] = __float_as_uint(Qs[base]);
                a[mb][1] = __float_as_uint(Qs[base + 8 * FQ_STR]);
                a[mb][2] = __float_as_uint(Qs[base + 4]);
                a[mb][3] = __float_as_uint(Qs[base + 8 * FQ_STR + 4]);
            }
            #pragma unroll
            for (int nb = 0; nb < 8; nb++) {
                unsigned bf[2];
                const int bbase = (nb * 8 + gid) * FK_STR + ks * 8 + tid4;
                bf[0] = __float_as_uint(Ks[bbase]);
                bf[1] = __float_as_uint(Ks[bbase + 4]);
                mma_tf32(S[0][nb], a[0], bf);
                mma_tf32(S[1][nb], a[1], bf);
            }
        }
        __syncthreads();       // all warps done reading K tile

        // prefetch next K tile (overlaps softmax + PV)
        if (t0 + 64 < SEQ) {
            #pragma unroll
            for (int i = 0; i < 8; i++) {
                const int idx = tid + i * 128;
                const int r = idx >> 4, c = idx & 15;
                cp_async16(Ks + r * FK_STR + c * 4,
                           Kp + (size_t)(t0 + 64 + r) * HDIM + c * 4);
            }
            cp_commit();
        }

        // ---- no-max softmax: p = bit ? exp(0.125*s) : 0 ----
        #pragma unroll
        for (int mb = 0; mb < 2; mb++) {
            #pragma unroll
            for (int h = 0; h < 2; h++) {
                const unsigned long long m64 = mbits[mb][h];
                float ls = 0.0f;
                #pragma unroll
                for (int nb = 0; nb < 8; nb++) {
                    const int pos = nb * 8 + 2 * tid4;
                    const float p0 = ((m64 >> pos) & 1ULL)
                                   ? __expf(0.125f * S[mb][nb][2 * h]) : 0.0f;
                    const float p1 = ((m64 >> (pos + 1)) & 1ULL)
                                   ? __expf(0.125f * S[mb][nb][2 * h + 1]) : 0.0f;
                    ls += p0 + p1;
                    S[mb][nb][2 * h]     = p0;
                    S[mb][nb][2 * h + 1] = p1;
                }
                lrow[mb][h] += ls;
            }
        }

        // wait for V(t); pending afterwards: only K(t+1) (if any)
        if (t0 + 64 < SEQ) cp_wait<1>(); else cp_wait<0>();
        __syncthreads();

        // ---- O += P @ V : shuffle-transpose P C-frag -> A-frag ----
        const int src0 = (lane & 28) | (tid4 >> 1);
        const int src1 = src0 + 2;
        const bool odd = (tid4 & 1);
        #pragma unroll
        for (int kt = 0; kt < 8; kt++) {
            unsigned a[2][4];
            #pragma unroll
            for (int mb = 0; mb < 2; mb++) {
                float e0 = __shfl_sync(0xffffffffu, S[mb][kt][0], src0);
                float o0 = __shfl_sync(0xffffffffu, S[mb][kt][1], src0);
                float e1 = __shfl_sync(0xffffffffu, S[mb][kt][0], src1);
                float o1 = __shfl_sync(0xffffffffu, S[mb][kt][1], src1);
                float e2 = __shfl_sync(0xffffffffu, S[mb][kt][2], src0);
                float o2 = __shfl_sync(0xffffffffu, S[mb][kt][3], src0);
                float e3 = __shfl_sync(0xffffffffu, S[mb][kt][2], src1);
                float o3 = __shfl_sync(0xffffffffu, S[mb][kt][3], src1);
                a[mb][0] = f2tf(odd ? o0 : e0);
                a[mb][1] = f2tf(odd ? o2 : e2);
                a[mb][2] = f2tf(odd ? o1 : e1);
                a[mb][3] = f2tf(odd ? o3 : e3);
            }
            #pragma unroll
            for (int nb = 0; nb < 8; nb++) {
                unsigned bf[2];
                const int vbase = (kt * 8 + tid4) * FV_STR + nb * 8 + gid;
                bf[0] = __float_as_uint(Vs[vbase]);
                bf[1] = __float_as_uint(Vs[vbase + 4 * FV_STR]);
                mma_tf32(O[0][nb], a[0], bf);
                mma_tf32(O[1][nb], a[1], bf);
            }
        }
        __syncthreads();       // all warps done reading V tile

        // prefetch next V tile (overlaps next QK)
        if (t0 + 64 < SEQ) {
            #pragma unroll
            for (int i = 0; i < 8; i++) {
                const int idx = tid + i * 128;
                const int r = idx >> 4, c = idx & 15;
                cp_async16(Vs + r * FV_STR + c * 4,
                           Vp + (size_t)(t0 + 64 + r) * HDIM + c * 4);
            }
            cp_commit();
        }
    }

    // ---- epilogue: reduce row sums once, normalize, store ----
    #pragma unroll
    for (int mb = 0; mb < 2; mb++) {
        #pragma unroll
        for (int h = 0; h < 2; h++) {
            float l = lrow[mb][h];
            l += __shfl_xor_sync(0xffffffffu, l, 1);
            l += __shfl_xor_sync(0xffffffffu, l, 2);
            const float linv = 1.0f / l;
            const int rg = f0 + w * 32 + mb * 16 + gid + 8 * h;
            float* op = out + ((size_t)b * SEQ + rg) * HIDDEN + nh * HDIM;
            #pragma unroll
            for (int nb = 0; nb < 8; nb++) {
                float2 v;
                v.x = O[mb][nb][2 * h] * linv;
                v.y = O[mb][nb][2 * h + 1] * linv;
                *(float2*)(op + nb * 8 + 2 * tid4) = v;
            }
        }
    }
}

// ---------------------------------------------------------------------------
// kernel_launch
// ---------------------------------------------------------------------------
extern "C" void kernel_launch(void* const* d_in, const int* in_sizes, int n_in,
                              void* d_out, int out_size)
{
    (void)in_sizes; (void)n_in; (void)out_size;

    const float* from_t = (const float*)d_in[0];
    const float* to_t   = (const float*)d_in[1];
    const int*   msk    = (const int*)d_in[2];
    const float* Wq     = (const float*)d_in[3];
    const float* bq     = (const float*)d_in[4];
    const float* Wk     = (const float*)d_in[5];
    const float* bk     = (const float*)d_in[6];
    const float* Wv     = (const float*)d_in[7];
    const float* bv     = (const float*)d_in[8];
    float* out = (float*)d_out;

    float *qp, *kp, *vp; unsigned* mb;
    cudaGetSymbolAddress((void**)&qp, g_Qs);
    cudaGetSymbolAddress((void**)&kp, g_Ks);
    cudaGetSymbolAddress((void**)&vp, g_Vs);
    cudaGetSymbolAddress((void**)&mb, g_Mbits);

    cudaFuncSetAttribute(gemm_mma_kernel,
                         cudaFuncAttributeMaxDynamicSharedMemorySize, GEMM_SMEM);
    cudaFuncSetAttribute(flash_mma_kernel,
                         cudaFuncAttributeMaxDynamicSharedMemorySize, ATT_SMEM);

    // pack mask to bits (independent of GEMM outputs)
    mask_bits_kernel<<<(MROWS * 32 + 255) / 256, 256>>>(msk, mb);

    dim3 gg(HIDDEN / 128, MROWS / 128, 3);   // (8, 32, 3)
    gemm_mma_kernel<<<gg, 256, GEMM_SMEM>>>(from_t, to_t, Wq, bq, Wk, bk,
                                            Wv, bv, qp, kp, vp);

    dim3 gf(SEQ / 128, BATCH * NHEADS);      // (16, 32)
    flash_mma_kernel<<<gf, 128, ATT_SMEM>>>(qp, kp, vp, mb, out);
}

// round 8
// speedup vs baseline: 1.1840x; 1.0436x over previous
#include <cuda_runtime.h>
#include <cuda_bf16.h>
#include <math.h>

// ---------------------------------------------------------------------------
// Attention_69226282877525: BERT-style MHA on sm_103a, tf32 mma.sync path.
//   B=2, F=T=2048, HIDDEN=1024, N_HEADS=16, HEAD_DIM=64
// R8 = R7 + flash re-tiled to f-tile 64 / 64-thread CTAs / 4 CTAs/SM to
// eliminate wave quantization (512 CTAs @ cap 444 was running 2 full waves).
// ---------------------------------------------------------------------------

#define BATCH   2
#define SEQ     2048
#define HIDDEN  1024
#define NHEADS  16
#define HDIM    64
#define MROWS   (BATCH * SEQ)      // 4096

// Scratch for Q/K/V in [B][N][S][H] layout, tf32-pre-rounded fp32 (16 MB each)
__device__ float g_Qs[(size_t)BATCH * NHEADS * SEQ * HDIM];
__device__ float g_Ks[(size_t)BATCH * NHEADS * SEQ * HDIM];
__device__ float g_Vs[(size_t)BATCH * NHEADS * SEQ * HDIM];
// Packed attention mask bits: [B][F][T/32] (1 MB)
__device__ unsigned g_Mbits[(size_t)BATCH * SEQ * (SEQ / 32)];

// --------------------------- helpers ---------------------------------------
__device__ __forceinline__ unsigned f2tf(float x) {
    unsigned r;
    asm("cvt.rna.tf32.f32 %0, %1;" : "=r"(r) : "f"(x));
    return r;
}
__device__ __forceinline__ float f2tf_f(float x) {
    return __uint_as_float(f2tf(x));
}
__device__ __forceinline__ void cvt4(float4& v) {
    v.x = f2tf_f(v.x); v.y = f2tf_f(v.y); v.z = f2tf_f(v.z); v.w = f2tf_f(v.w);
}
__device__ __forceinline__ void mma_tf32(float c[4], const unsigned a[4],
                                         const unsigned b[2]) {
    asm volatile(
        "mma.sync.aligned.m16n8k8.row.col.f32.tf32.tf32.f32 "
        "{%0,%1,%2,%3}, {%4,%5,%6,%7}, {%8,%9}, {%0,%1,%2,%3};\n"
        : "+f"(c[0]), "+f"(c[1]), "+f"(c[2]), "+f"(c[3])
        : "r"(a[0]), "r"(a[1]), "r"(a[2]), "r"(a[3]), "r"(b[0]), "r"(b[1]));
}
__device__ __forceinline__ void cp_async16(float* dst_smem, const float* src) {
    unsigned d = (unsigned)__cvta_generic_to_shared(dst_smem);
    asm volatile("cp.async.cg.shared.global [%0], [%1], 16;" :: "r"(d), "l"(src));
}
__device__ __forceinline__ void cp_commit() {
    asm volatile("cp.async.commit_group;");
}
template<int N> __device__ __forceinline__ void cp_wait() {
    asm volatile("cp.async.wait_group %0;" :: "n"(N));
}

// ---------------------------------------------------------------------------
// Pack mask [B,F,T] int32 -> bitmask [B,F,T/32]. One warp per (b,f) row.
// ---------------------------------------------------------------------------
__global__ __launch_bounds__(256) void mask_bits_kernel(
    const int* __restrict__ mask, unsigned* __restrict__ bits)
{
    const int gw   = (blockIdx.x * 256 + threadIdx.x) >> 5;   // row index
    const int lane = threadIdx.x & 31;
    if (gw >= BATCH * SEQ) return;
    const int* mp = mask + (size_t)gw * SEQ;
    unsigned* bp  = bits + (size_t)gw * (SEQ / 32);
    #pragma unroll 4
    for (int c = 0; c < SEQ / 32; c++) {
        const int v = mp[c * 32 + lane];
        const unsigned w = __ballot_sync(0xffffffffu, v != 0);
        if (lane == 0) bp[c] = w;
    }
}

// ---------------------------------------------------------------------------
// Merged QKV projection GEMM (tf32 mma): blockIdx.z in {Q,K,V}.
// CTA 256 thr, tile 128x128, ktile 16, 8 warps (4m x 2n), warp tile 32x64.
// ---------------------------------------------------------------------------
#define GA_STR 20
#define GB_STR 136
#define GEMM_SMEM ((2 * 128 * GA_STR + 2 * 16 * GB_STR) * 4)   // 37888 bytes

__global__ __launch_bounds__(256, 2) void gemm_mma_kernel(
    const float* __restrict__ Xq, const float* __restrict__ Xkv,
    const float* __restrict__ Wq, const float* __restrict__ bq,
    const float* __restrict__ Wk, const float* __restrict__ bk,
    const float* __restrict__ Wv, const float* __restrict__ bv,
    float* __restrict__ oq, float* __restrict__ ok, float* __restrict__ ov)
{
    extern __shared__ float smg[];
    float* As = smg;                       // [2][128][GA_STR]
    float* Bs = smg + 2 * 128 * GA_STR;    // [2][16][GB_STR]

    const float* X; const float* W; const float* bias; float* out;
    if (blockIdx.z == 0)      { X = Xq;  W = Wq; bias = bq; out = oq; }
    else if (blockIdx.z == 1) { X = Xkv; W = Wk; bias = bk; out = ok; }
    else                      { X = Xkv; W = Wv; bias = bv; out = ov; }

    const int tid  = threadIdx.x;
    const int w    = tid >> 5;
    const int lane = tid & 31;
    const int gid  = lane >> 2;
    const int tid4 = lane & 3;
    const int wm   = w & 3;
    const int wn   = w >> 2;
    const int row0 = blockIdx.y * 128;
    const int col0 = blockIdx.x * 128;

    float4 ar[2], br[2];

    #pragma unroll
    for (int i = 0; i < 2; i++) {
        const int idx = tid + i * 256;
        { const int r = idx >> 2, c4 = idx & 3;
          ar[i] = *(const float4*)(X + (size_t)(row0 + r) * HIDDEN + c4 * 4); }
        { const int r = idx >> 5, c4 = idx & 31;
          br[i] = *(const float4*)(W + (size_t)r * HIDDEN + col0 + c4 * 4); }
    }
    #pragma unroll
    for (int i = 0; i < 2; i++) {
        const int idx = tid + i * 256;
        cvt4(ar[i]); cvt4(br[i]);
        { const int r = idx >> 2, c4 = idx & 3;
          *(float4*)(As + r * GA_STR + c4 * 4) = ar[i]; }
        { const int r = idx >> 5, c4 = idx & 31;
          *(float4*)(Bs + r * GB_STR + c4 * 4) = br[i]; }
    }
    __syncthreads();

    float C[2][8][4] = {};

    for (int kt = 0; kt < 64; kt++) {
        const int buf = kt & 1;
        if (kt < 63) {
            const int k0 = (kt + 1) * 16;
            #pragma unroll
            for (int i = 0; i < 2; i++) {
                const int idx = tid + i * 256;
                { const int r = idx >> 2, c4 = idx & 3;
                  ar[i] = *(const float4*)(X + (size_t)(row0 + r) * HIDDEN + k0 + c4 * 4); }
                { const int r = idx >> 5, c4 = idx & 31;
                  br[i] = *(const float4*)(W + (size_t)(k0 + r) * HIDDEN + col0 + c4 * 4); }
            }
        }
        const float* Ab = As + buf * 128 * GA_STR;
        const float* Bb = Bs + buf * 16 * GB_STR;
        #pragma unroll
        for (int ks = 0; ks < 2; ks++) {
            unsigned a[2][4];
            #pragma unroll
            for (int mb = 0; mb < 2; mb++) {
                const int base = (wm * 32 + mb * 16 + gid) * GA_STR + ks * 8 + tid4;
                a[mb][0] = __float_as_uint(Ab[base]);
                a[mb][1] = __float_as_uint(Ab[base + 8 * GA_STR]);
                a[mb][2] = __float_as_uint(Ab[base + 4]);
                a[mb][3] = __float_as_uint(Ab[base + 8 * GA_STR + 4]);
            }
            #pragma unroll
            for (int nb = 0; nb < 8; nb++) {
                unsigned bf[2];
                const int bbase = (ks * 8 + tid4) * GB_STR + wn * 64 + nb * 8 + gid;
                bf[0] = __float_as_uint(Bb[bbase]);
                bf[1] = __float_as_uint(Bb[bbase + 4 * GB_STR]);
                mma_tf32(C[0][nb], a[0], bf);
                mma_tf32(C[1][nb], a[1], bf);
            }
        }
        if (kt < 63) {
            float* An = As + ((kt + 1) & 1) * 128 * GA_STR;
            float* Bn = Bs + ((kt + 1) & 1) * 16 * GB_STR;
            #pragma unroll
            for (int i = 0; i < 2; i++) {
                const int idx = tid + i * 256;
                cvt4(ar[i]); cvt4(br[i]);
                { const int r = idx >> 2, c4 = idx & 3;
                  *(float4*)(An + r * GA_STR + c4 * 4) = ar[i]; }
                { const int r = idx >> 5, c4 = idx & 31;
                  *(float4*)(Bn + r * GB_STR + c4 * 4) = br[i]; }
            }
        }
        __syncthreads();
    }

    // epilogue: bias + tf32 round + transpose-store to [B][N][S][H]
    const int colbase = col0 + wn * 64;
    const int nhead   = colbase >> 6;
    #pragma unroll
    for (int mb = 0; mb < 2; mb++) {
        #pragma unroll
        for (int h = 0; h < 2; h++) {
            const int row = row0 + wm * 32 + mb * 16 + gid + 8 * h;
            const int b   = row >> 11;
            const int s   = row & 2047;
            float* op = out + (((size_t)b * NHEADS + nhead) * SEQ + s) * HDIM;
            #pragma unroll
            for (int nb = 0; nb < 8; nb++) {
                const int hh = nb * 8 + 2 * tid4;
                float2 v;
                v.x = f2tf_f(C[mb][nb][2 * h]     + bias[colbase + hh]);
                v.y = f2tf_f(C[mb][nb][2 * h + 1] + bias[colbase + hh + 1]);
                *(float2*)(op + hh) = v;
            }
        }
    }
}

// ---------------------------------------------------------------------------
// Flash attention (tf32 mma): CTA 64 thr (2 warps x 32 rows), f-tile 64,
// T-tile 64. 4 CTAs/SM (53.2KB SMEM) -> grid 1024 fills the chip without
// wave quantization. No-max softmax; split K/V cp.async groups; bitmask.
// ---------------------------------------------------------------------------
#define FQ_STR 68
#define FK_STR 68
#define FV_STR 72
#define ATT_SMEM ((64 * FQ_STR + 64 * FK_STR + 64 * FV_STR) * 4)  // 53248

__global__ __launch_bounds__(64, 4) void flash_mma_kernel(
    const float* __restrict__ Q, const float* __restrict__ K,
    const float* __restrict__ V, const unsigned* __restrict__ mbitsg,
    float* __restrict__ out)
{
    extern __shared__ float sm[];
    float* Qs = sm;                       // [64][68]
    float* Ks = Qs + 64 * FQ_STR;         // [64][68]
    float* Vs = Ks + 64 * FK_STR;         // [64][72]

    const int tid  = threadIdx.x;         // 64
    const int w    = tid >> 5;            // 0..1
    const int lane = tid & 31;
    const int gid  = lane >> 2;
    const int tid4 = lane & 3;

    const int bn = blockIdx.y;            // b*16 + head
    const int b  = bn >> 4;
    const int nh = bn & 15;
    const int f0 = blockIdx.x * 64;

    const float* Qp = Q + ((size_t)bn * SEQ + f0) * HDIM;
    const float* Kp = K + (size_t)bn * SEQ * HDIM;
    const float* Vp = V + (size_t)bn * SEQ * HDIM;
    const unsigned* Mb = mbitsg + (size_t)b * SEQ * (SEQ / 32);

    // prologue: stage Q + K0 (group A), V0 (group B). 64 threads.
    #pragma unroll
    for (int i = 0; i < 16; i++) {
        const int idx = tid + i * 64;
        const int r = idx >> 4, c = idx & 15;
        cp_async16(Qs + r * FQ_STR + c * 4, Qp + (size_t)r * HDIM + c * 4);
        cp_async16(Ks + r * FK_STR + c * 4, Kp + (size_t)r * HDIM + c * 4);
    }
    cp_commit();
    #pragma unroll
    for (int i = 0; i < 16; i++) {
        const int idx = tid + i * 64;
        const int r = idx >> 4, c = idx & 15;
        cp_async16(Vs + r * FV_STR + c * 4, Vp + (size_t)r * HDIM + c * 4);
    }
    cp_commit();

    float O[2][8][4] = {};
    float lrow[2][2] = {};

    for (int t0 = 0; t0 < SEQ; t0 += 64) {
        cp_wait<1>();          // Q + K(t) ready (V(t) may still be in flight)
        __syncthreads();

        // prefetch mask bits for this tile (hidden behind QK mma)
        unsigned long long mbits[2][2];
        #pragma unroll
        for (int mb = 0; mb < 2; mb++)
            #pragma unroll
            for (int h = 0; h < 2; h++) {
                const int rg = f0 + w * 32 + mb * 16 + gid + 8 * h;
                const uint2 mm = *(const uint2*)(Mb + (size_t)rg * (SEQ / 32) + (t0 >> 5));
                mbits[mb][h] = (unsigned long long)mm.x |
                               ((unsigned long long)mm.y << 32);
            }

        // ---- S = Q @ K^T ----
        float S[2][8][4] = {};
        #pragma unroll
        for (int ks = 0; ks < 8; ks++) {
            unsigned a[2][4];
            #pragma unroll
            for (int mb = 0; mb < 2; mb++) {
                const int base = (w * 32 + mb * 16 + gid) * FQ_STR + ks * 8 + tid4;
                a[mb][0] = __float_as_uint(Qs[base]);
                a[mb][1] = __float_as_uint(Qs[base + 8 * FQ_STR]);
                a[mb][2] = __float_as_uint(Qs[base + 4]);
                a[mb][3] = __float_as_uint(Qs[base + 8 * FQ_STR + 4]);
            }
            #pragma unroll
            for (int nb = 0; nb < 8; nb++) {
                unsigned bf[2];
                const int bbase = (nb * 8 + gid) * FK_STR + ks * 8 + tid4;
                bf[0] = __float_as_uint(Ks[bbase]);
                bf[1] = __float_as_uint(Ks[bbase + 4]);
                mma_tf32(S[0][nb], a[0], bf);
                mma_tf32(S[1][nb], a[1], bf);
            }
        }
        __syncthreads();       // all warps done reading K tile

        // prefetch next K tile (overlaps softmax + PV)
        if (t0 + 64 < SEQ) {
            #pragma unroll
            for (int i = 0; i < 16; i++) {
                const int idx = tid + i * 64;
                const int r = idx >> 4, c = idx & 15;
                cp_async16(Ks + r * FK_STR + c * 4,
                           Kp + (size_t)(t0 + 64 + r) * HDIM + c * 4);
            }
            cp_commit();
        }

        // ---- no-max softmax: p = bit ? exp(0.125*s) : 0 ----
        #pragma unroll
        for (int mb = 0; mb < 2; mb++) {
            #pragma unroll
            for (int h = 0; h < 2; h++) {
                const unsigned long long m64 = mbits[mb][h];
                float ls = 0.0f;
                #pragma unroll
                for (int nb = 0; nb < 8; nb++) {
                    const int pos = nb * 8 + 2 * tid4;
                    const float p0 = ((m64 >> pos) & 1ULL)
                                   ? __expf(0.125f * S[mb][nb][2 * h]) : 0.0f;
                    const float p1 = ((m64 >> (pos + 1)) & 1ULL)
                                   ? __expf(0.125f * S[mb][nb][2 * h + 1]) : 0.0f;
                    ls += p0 + p1;
                    S[mb][nb][2 * h]     = p0;
                    S[mb][nb][2 * h + 1] = p1;
                }
                lrow[mb][h] += ls;
            }
        }

        // wait for V(t); pending afterwards: only K(t+1) (if any)
        if (t0 + 64 < SEQ) cp_wait<1>(); else cp_wait<0>();
        __syncthreads();

        // ---- O += P @ V : shuffle-transpose P C-frag -> A-frag ----
        const int src0 = (lane & 28) | (tid4 >> 1);
        const int src1 = src0 + 2;
        const bool odd = (tid4 & 1);
        #pragma unroll
        for (int kt = 0; kt < 8; kt++) {
            unsigned a[2][4];
            #pragma unroll
            for (int mb = 0; mb < 2; mb++) {
                float e0 = __shfl_sync(0xffffffffu, S[mb][kt][0], src0);
                float o0 = __shfl_sync(0xffffffffu, S[mb][kt][1], src0);
                float e1 = __shfl_sync(0xffffffffu, S[mb][kt][0], src1);
                float o1 = __shfl_sync(0xffffffffu, S[mb][kt][1], src1);
                float e2 = __shfl_sync(0xffffffffu, S[mb][kt][2], src0);
                float o2 = __shfl_sync(0xffffffffu, S[mb][kt][3], src0);
                float e3 = __shfl_sync(0xffffffffu, S[mb][kt][2], src1);
                float o3 = __shfl_sync(0xffffffffu, S[mb][kt][3], src1);
                a[mb][0] = f2tf(odd ? o0 : e0);
                a[mb][1] = f2tf(odd ? o2 : e2);
                a[mb][2] = f2tf(odd ? o1 : e1);
                a[mb][3] = f2tf(odd ? o3 : e3);
            }
            #pragma unroll
            for (int nb = 0; nb < 8; nb++) {
                unsigned bf[2];
                const int vbase = (kt * 8 + tid4) * FV_STR + nb * 8 + gid;
                bf[0] = __float_as_uint(Vs[vbase]);
                bf[1] = __float_as_uint(Vs[vbase + 4 * FV_STR]);
                mma_tf32(O[0][nb], a[0], bf);
                mma_tf32(O[1][nb], a[1], bf);
            }
        }
        __syncthreads();       // all warps done reading V tile

        // prefetch next V tile (overlaps next QK)
        if (t0 + 64 < SEQ) {
            #pragma unroll
            for (int i = 0; i < 16; i++) {
                const int idx = tid + i * 64;
                const int r = idx >> 4, c = idx & 15;
                cp_async16(Vs + r * FV_STR + c * 4,
                           Vp + (size_t)(t0 + 64 + r) * HDIM + c * 4);
            }
            cp_commit();
        }
    }

    // ---- epilogue: reduce row sums once, normalize, store ----
    #pragma unroll
    for (int mb = 0; mb < 2; mb++) {
        #pragma unroll
        for (int h = 0; h < 2; h++) {
            float l = lrow[mb][h];
            l += __shfl_xor_sync(0xffffffffu, l, 1);
            l += __shfl_xor_sync(0xffffffffu, l, 2);
            const float linv = 1.0f / l;
            const int rg = f0 + w * 32 + mb * 16 + gid + 8 * h;
            float* op = out + ((size_t)b * SEQ + rg) * HIDDEN + nh * HDIM;
            #pragma unroll
            for (int nb = 0; nb < 8; nb++) {
                float2 v;
                v.x = O[mb][nb][2 * h] * linv;
                v.y = O[mb][nb][2 * h + 1] * linv;
                *(float2*)(op + nb * 8 + 2 * tid4) = v;
            }
        }
    }
}

// ---------------------------------------------------------------------------
// kernel_launch
// ---------------------------------------------------------------------------
extern "C" void kernel_launch(void* const* d_in, const int* in_sizes, int n_in,
                              void* d_out, int out_size)
{
    (void)in_sizes; (void)n_in; (void)out_size;

    const float* from_t = (const float*)d_in[0];
    const float* to_t   = (const float*)d_in[1];
    const int*   msk    = (const int*)d_in[2];
    const float* Wq     = (const float*)d_in[3];
    const float* bq     = (const float*)d_in[4];
    const float* Wk     = (const float*)d_in[5];
    const float* bk     = (const float*)d_in[6];
    const float* Wv     = (const float*)d_in[7];
    const float* bv     = (const float*)d_in[8];
    float* out = (float*)d_out;

    float *qp, *kp, *vp; unsigned* mb;
    cudaGetSymbolAddress((void**)&qp, g_Qs);
    cudaGetSymbolAddress((void**)&kp, g_Ks);
    cudaGetSymbolAddress((void**)&vp, g_Vs);
    cudaGetSymbolAddress((void**)&mb, g_Mbits);

    cudaFuncSetAttribute(gemm_mma_kernel,
                         cudaFuncAttributeMaxDynamicSharedMemorySize, GEMM_SMEM);
    cudaFuncSetAttribute(flash_mma_kernel,
                         cudaFuncAttributeMaxDynamicSharedMemorySize, ATT_SMEM);

    // pack mask to bits (independent of GEMM outputs)
    mask_bits_kernel<<<(MROWS * 32 + 255) / 256, 256>>>(msk, mb);

    dim3 gg(HIDDEN / 128, MROWS / 128, 3);   // (8, 32, 3)
    gemm_mma_kernel<<<gg, 256, GEMM_SMEM>>>(from_t, to_t, Wq, bq, Wk, bk,
                                            Wv, bv, qp, kp, vp);

    dim3 gf(SEQ / 64, BATCH * NHEADS);       // (32, 32) = 1024 CTAs
    flash_mma_kernel<<<gf, 64, ATT_SMEM>>>(qp, kp, vp, mb, out);
}

// round 9
// speedup vs baseline: 1.1984x; 1.0122x over previous
#include <cuda_runtime.h>
#include <cuda_bf16.h>
#include <math.h>

// ---------------------------------------------------------------------------
// Attention_69226282877525: BERT-style MHA on sm_103a, tf32 mma.sync path.
//   B=2, F=T=2048, HIDDEN=1024, N_HEADS=16, HEAD_DIM=64
// R9 = R8 + flash CTA re-warped: 128 thr = 4 warps x 16 f-rows (was 2x32).
// Same SMEM (53KB, 4 CTAs/SM) but 16 warps/SM for latency hiding.
// ---------------------------------------------------------------------------

#define BATCH   2
#define SEQ     2048
#define HIDDEN  1024
#define NHEADS  16
#define HDIM    64
#define MROWS   (BATCH * SEQ)      // 4096

// Scratch for Q/K/V in [B][N][S][H] layout, tf32-pre-rounded fp32 (16 MB each)
__device__ float g_Qs[(size_t)BATCH * NHEADS * SEQ * HDIM];
__device__ float g_Ks[(size_t)BATCH * NHEADS * SEQ * HDIM];
__device__ float g_Vs[(size_t)BATCH * NHEADS * SEQ * HDIM];
// Packed attention mask bits: [B][F][T/32] (1 MB)
__device__ unsigned g_Mbits[(size_t)BATCH * SEQ * (SEQ / 32)];

// --------------------------- helpers ---------------------------------------
__device__ __forceinline__ unsigned f2tf(float x) {
    unsigned r;
    asm("cvt.rna.tf32.f32 %0, %1;" : "=r"(r) : "f"(x));
    return r;
}
__device__ __forceinline__ float f2tf_f(float x) {
    return __uint_as_float(f2tf(x));
}
__device__ __forceinline__ void cvt4(float4& v) {
    v.x = f2tf_f(v.x); v.y = f2tf_f(v.y); v.z = f2tf_f(v.z); v.w = f2tf_f(v.w);
}
__device__ __forceinline__ void mma_tf32(float c[4], const unsigned a[4],
                                         const unsigned b[2]) {
    asm volatile(
        "mma.sync.aligned.m16n8k8.row.col.f32.tf32.tf32.f32 "
        "{%0,%1,%2,%3}, {%4,%5,%6,%7}, {%8,%9}, {%0,%1,%2,%3};\n"
        : "+f"(c[0]), "+f"(c[1]), "+f"(c[2]), "+f"(c[3])
        : "r"(a[0]), "r"(a[1]), "r"(a[2]), "r"(a[3]), "r"(b[0]), "r"(b[1]));
}
__device__ __forceinline__ void cp_async16(float* dst_smem, const float* src) {
    unsigned d = (unsigned)__cvta_generic_to_shared(dst_smem);
    asm volatile("cp.async.cg.shared.global [%0], [%1], 16;" :: "r"(d), "l"(src));
}
__device__ __forceinline__ void cp_commit() {
    asm volatile("cp.async.commit_group;");
}
template<int N> __device__ __forceinline__ void cp_wait() {
    asm volatile("cp.async.wait_group %0;" :: "n"(N));
}

// ---------------------------------------------------------------------------
// Pack mask [B,F,T] int32 -> bitmask [B,F,T/32]. One warp per (b,f) row.
// ---------------------------------------------------------------------------
__global__ __launch_bounds__(256) void mask_bits_kernel(
    const int* __restrict__ mask, unsigned* __restrict__ bits)
{
    const int gw   = (blockIdx.x * 256 + threadIdx.x) >> 5;   // row index
    const int lane = threadIdx.x & 31;
    if (gw >= BATCH * SEQ) return;
    const int* mp = mask + (size_t)gw * SEQ;
    unsigned* bp  = bits + (size_t)gw * (SEQ / 32);
    #pragma unroll 4
    for (int c = 0; c < SEQ / 32; c++) {
        const int v = mp[c * 32 + lane];
        const unsigned w = __ballot_sync(0xffffffffu, v != 0);
        if (lane == 0) bp[c] = w;
    }
}

// ---------------------------------------------------------------------------
// Merged QKV projection GEMM (tf32 mma): blockIdx.z in {Q,K,V}.
// CTA 256 thr, tile 128x128, ktile 16, 8 warps (4m x 2n), warp tile 32x64.
// ---------------------------------------------------------------------------
#define GA_STR 20
#define GB_STR 136
#define GEMM_SMEM ((2 * 128 * GA_STR + 2 * 16 * GB_STR) * 4)   // 37888 bytes

__global__ __launch_bounds__(256, 2) void gemm_mma_kernel(
    const float* __restrict__ Xq, const float* __restrict__ Xkv,
    const float* __restrict__ Wq, const float* __restrict__ bq,
    const float* __restrict__ Wk, const float* __restrict__ bk,
    const float* __restrict__ Wv, const float* __restrict__ bv,
    float* __restrict__ oq, float* __restrict__ ok, float* __restrict__ ov)
{
    extern __shared__ float smg[];
    float* As = smg;                       // [2][128][GA_STR]
    float* Bs = smg + 2 * 128 * GA_STR;    // [2][16][GB_STR]

    const float* X; const float* W; const float* bias; float* out;
    if (blockIdx.z == 0)      { X = Xq;  W = Wq; bias = bq; out = oq; }
    else if (blockIdx.z == 1) { X = Xkv; W = Wk; bias = bk; out = ok; }
    else                      { X = Xkv; W = Wv; bias = bv; out = ov; }

    const int tid  = threadIdx.x;
    const int w    = tid >> 5;
    const int lane = tid & 31;
    const int gid  = lane >> 2;
    const int tid4 = lane & 3;
    const int wm   = w & 3;
    const int wn   = w >> 2;
    const int row0 = blockIdx.y * 128;
    const int col0 = blockIdx.x * 128;

    float4 ar[2], br[2];

    #pragma unroll
    for (int i = 0; i < 2; i++) {
        const int idx = tid + i * 256;
        { const int r = idx >> 2, c4 = idx & 3;
          ar[i] = *(const float4*)(X + (size_t)(row0 + r) * HIDDEN + c4 * 4); }
        { const int r = idx >> 5, c4 = idx & 31;
          br[i] = *(const float4*)(W + (size_t)r * HIDDEN + col0 + c4 * 4); }
    }
    #pragma unroll
    for (int i = 0; i < 2; i++) {
        const int idx = tid + i * 256;
        cvt4(ar[i]); cvt4(br[i]);
        { const int r = idx >> 2, c4 = idx & 3;
          *(float4*)(As + r * GA_STR + c4 * 4) = ar[i]; }
        { const int r = idx >> 5, c4 = idx & 31;
          *(float4*)(Bs + r * GB_STR + c4 * 4) = br[i]; }
    }
    __syncthreads();

    float C[2][8][4] = {};

    for (int kt = 0; kt < 64; kt++) {
        const int buf = kt & 1;
        if (kt < 63) {
            const int k0 = (kt + 1) * 16;
            #pragma unroll
            for (int i = 0; i < 2; i++) {
                const int idx = tid + i * 256;
                { const int r = idx >> 2, c4 = idx & 3;
                  ar[i] = *(const float4*)(X + (size_t)(row0 + r) * HIDDEN + k0 + c4 * 4); }
                { const int r = idx >> 5, c4 = idx & 31;
                  br[i] = *(const float4*)(W + (size_t)(k0 + r) * HIDDEN + col0 + c4 * 4); }
            }
        }
        const float* Ab = As + buf * 128 * GA_STR;
        const float* Bb = Bs + buf * 16 * GB_STR;
        #pragma unroll
        for (int ks = 0; ks < 2; ks++) {
            unsigned a[2][4];
            #pragma unroll
            for (int mb = 0; mb < 2; mb++) {
                const int base = (wm * 32 + mb * 16 + gid) * GA_STR + ks * 8 + tid4;
                a[mb][0] = __float_as_uint(Ab[base]);
                a[mb][1] = __float_as_uint(Ab[base + 8 * GA_STR]);
                a[mb][2] = __float_as_uint(Ab[base + 4]);
                a[mb][3] = __float_as_uint(Ab[base + 8 * GA_STR + 4]);
            }
            #pragma unroll
            for (int nb = 0; nb < 8; nb++) {
                unsigned bf[2];
                const int bbase = (ks * 8 + tid4) * GB_STR + wn * 64 + nb * 8 + gid;
                bf[0] = __float_as_uint(Bb[bbase]);
                bf[1] = __float_as_uint(Bb[bbase + 4 * GB_STR]);
                mma_tf32(C[0][nb], a[0], bf);
                mma_tf32(C[1][nb], a[1], bf);
            }
        }
        if (kt < 63) {
            float* An = As + ((kt + 1) & 1) * 128 * GA_STR;
            float* Bn = Bs + ((kt + 1) & 1) * 16 * GB_STR;
            #pragma unroll
            for (int i = 0; i < 2; i++) {
                const int idx = tid + i * 256;
                cvt4(ar[i]); cvt4(br[i]);
                { const int r = idx >> 2, c4 = idx & 3;
                  *(float4*)(An + r * GA_STR + c4 * 4) = ar[i]; }
                { const int r = idx >> 5, c4 = idx & 31;
                  *(float4*)(Bn + r * GB_STR + c4 * 4) = br[i]; }
            }
        }
        __syncthreads();
    }

    // epilogue: bias + tf32 round + transpose-store to [B][N][S][H]
    const int colbase = col0 + wn * 64;
    const int nhead   = colbase >> 6;
    #pragma unroll
    for (int mb = 0; mb < 2; mb++) {
        #pragma unroll
        for (int h = 0; h < 2; h++) {
            const int row = row0 + wm * 32 + mb * 16 + gid + 8 * h;
            const int b   = row >> 11;
            const int s   = row & 2047;
            float* op = out + (((size_t)b * NHEADS + nhead) * SEQ + s) * HDIM;
            #pragma unroll
            for (int nb = 0; nb < 8; nb++) {
                const int hh = nb * 8 + 2 * tid4;
                float2 v;
                v.x = f2tf_f(C[mb][nb][2 * h]     + bias[colbase + hh]);
                v.y = f2tf_f(C[mb][nb][2 * h + 1] + bias[colbase + hh + 1]);
                *(float2*)(op + hh) = v;
            }
        }
    }
}

// ---------------------------------------------------------------------------
// Flash attention (tf32 mma): CTA 128 thr = 4 warps x 16 f-rows, f-tile 64,
// T-tile 64, 4 CTAs/SM (53.2KB SMEM) -> 16 warps/SM for latency hiding.
// No-max softmax; split K/V cp.async groups; bitmask.
// ---------------------------------------------------------------------------
#define FQ_STR 68
#define FK_STR 68
#define FV_STR 72
#define ATT_SMEM ((64 * FQ_STR + 64 * FK_STR + 64 * FV_STR) * 4)  // 53248

__global__ __launch_bounds__(128, 4) void flash_mma_kernel(
    const float* __restrict__ Q, const float* __restrict__ K,
    const float* __restrict__ V, const unsigned* __restrict__ mbitsg,
    float* __restrict__ out)
{
    extern __shared__ float sm[];
    float* Qs = sm;                       // [64][68]
    float* Ks = Qs + 64 * FQ_STR;         // [64][68]
    float* Vs = Ks + 64 * FK_STR;         // [64][72]

    const int tid  = threadIdx.x;         // 128
    const int w    = tid >> 5;            // 0..3 -> f-rows w*16..w*16+15
    const int lane = tid & 31;
    const int gid  = lane >> 2;
    const int tid4 = lane & 3;

    const int bn = blockIdx.y;            // b*16 + head
    const int b  = bn >> 4;
    const int nh = bn & 15;
    const int f0 = blockIdx.x * 64;

    const float* Qp = Q + ((size_t)bn * SEQ + f0) * HDIM;
    const float* Kp = K + (size_t)bn * SEQ * HDIM;
    const float* Vp = V + (size_t)bn * SEQ * HDIM;
    const unsigned* Mb = mbitsg + (size_t)b * SEQ * (SEQ / 32);

    // prologue: stage Q + K0 (group A), V0 (group B). 128 threads.
    #pragma unroll
    for (int i = 0; i < 8; i++) {
        const int idx = tid + i * 128;
        const int r = idx >> 4, c = idx & 15;
        cp_async16(Qs + r * FQ_STR + c * 4, Qp + (size_t)r * HDIM + c * 4);
        cp_async16(Ks + r * FK_STR + c * 4, Kp + (size_t)r * HDIM + c * 4);
    }
    cp_commit();
    #pragma unroll
    for (int i = 0; i < 8; i++) {
        const int idx = tid + i * 128;
        const int r = idx >> 4, c = idx & 15;
        cp_async16(Vs + r * FV_STR + c * 4, Vp + (size_t)r * HDIM + c * 4);
    }
    cp_commit();

    float O[8][4] = {};
    float lrow[2] = {};

    for (int t0 = 0; t0 < SEQ; t0 += 64) {
        cp_wait<1>();          // Q + K(t) ready (V(t) may still be in flight)
        __syncthreads();

        // prefetch mask bits for this tile (hidden behind QK mma)
        unsigned long long mbits[2];
        #pragma unroll
        for (int h = 0; h < 2; h++) {
            const int rg = f0 + w * 16 + gid + 8 * h;
            const uint2 mm = *(const uint2*)(Mb + (size_t)rg * (SEQ / 32) + (t0 >> 5));
            mbits[h] = (unsigned long long)mm.x |
                       ((unsigned long long)mm.y << 32);
        }

        // ---- S = Q @ K^T (warp tile 16x64) ----
        float S[8][4] = {};
        #pragma unroll
        for (int ks = 0; ks < 8; ks++) {
            unsigned a[4];
            const int base = (w * 16 + gid) * FQ_STR + ks * 8 + tid4;
            a[0] = __float_as_uint(Qs[base]);
            a[1] = __float_as_uint(Qs[base + 8 * FQ_STR]);
            a[2] = __float_as_uint(Qs[base + 4]);
            a[3] = __float_as_uint(Qs[base + 8 * FQ_STR + 4]);
            #pragma unroll
            for (int nb = 0; nb < 8; nb++) {
                unsigned bf[2];
                const int bbase = (nb * 8 + gid) * FK_STR + ks * 8 + tid4;
                bf[0] = __float_as_uint(Ks[bbase]);
                bf[1] = __float_as_uint(Ks[bbase + 4]);
                mma_tf32(S[nb], a, bf);
            }
        }
        __syncthreads();       // all warps done reading K tile

        // prefetch next K tile (overlaps softmax + PV)
        if (t0 + 64 < SEQ) {
            #pragma unroll
            for (int i = 0; i < 8; i++) {
                const int idx = tid + i * 128;
                const int r = idx >> 4, c = idx & 15;
                cp_async16(Ks + r * FK_STR + c * 4,
                           Kp + (size_t)(t0 + 64 + r) * HDIM + c * 4);
            }
            cp_commit();
        }

        // ---- no-max softmax: p = bit ? exp(0.125*s) : 0 ----
        #pragma unroll
        for (int h = 0; h < 2; h++) {
            const unsigned long long m64 = mbits[h];
            float ls = 0.0f;
            #pragma unroll
            for (int nb = 0; nb < 8; nb++) {
                const int pos = nb * 8 + 2 * tid4;
                const float p0 = ((m64 >> pos) & 1ULL)
                               ? __expf(0.125f * S[nb][2 * h]) : 0.0f;
                const float p1 = ((m64 >> (pos + 1)) & 1ULL)
                               ? __expf(0.125f * S[nb][2 * h + 1]) : 0.0f;
                ls += p0 + p1;
                S[nb][2 * h]     = p0;
                S[nb][2 * h + 1] = p1;
            }
            lrow[h] += ls;
        }

        // wait for V(t); pending afterwards: only K(t+1) (if any)
        if (t0 + 64 < SEQ) cp_wait<1>(); else cp_wait<0>();
        __syncthreads();

        // ---- O += P @ V : shuffle-transpose P C-frag -> A-frag ----
        const int src0 = (lane & 28) | (tid4 >> 1);
        const int src1 = src0 + 2;
        const bool odd = (tid4 & 1);
        #pragma unroll
        for (int kt = 0; kt < 8; kt++) {
            unsigned a[4];
            {
                float e0 = __shfl_sync(0xffffffffu, S[kt][0], src0);
                float o0 = __shfl_sync(0xffffffffu, S[kt][1], src0);
                float e1 = __shfl_sync(0xffffffffu, S[kt][0], src1);
                float o1 = __shfl_sync(0xffffffffu, S[kt][1], src1);
                float e2 = __shfl_sync(0xffffffffu, S[kt][2], src0);
                float o2 = __shfl_sync(0xffffffffu, S[kt][3], src0);
                float e3 = __shfl_sync(0xffffffffu, S[kt][2], src1);
                float o3 = __shfl_sync(0xffffffffu, S[kt][3], src1);
                a[0] = f2tf(odd ? o0 : e0);
                a[1] = f2tf(odd ? o2 : e2);
                a[2] = f2tf(odd ? o1 : e1);
                a[3] = f2tf(odd ? o3 : e3);
            }
            #pragma unroll
            for (int nb = 0; nb < 8; nb++) {
                unsigned bf[2];
                const int vbase = (kt * 8 + tid4) * FV_STR + nb * 8 + gid;
                bf[0] = __float_as_uint(Vs[vbase]);
                bf[1] = __float_as_uint(Vs[vbase + 4 * FV_STR]);
                mma_tf32(O[nb], a, bf);
            }
        }
        __syncthreads();       // all warps done reading V tile

        // prefetch next V tile (overlaps next QK)
        if (t0 + 64 < SEQ) {
            #pragma unroll
            for (int i = 0; i < 8; i++) {
                const int idx = tid + i * 128;
                const int r = idx >> 4, c = idx & 15;
                cp_async16(Vs + r * FV_STR + c * 4,
                           Vp + (size_t)(t0 + 64 + r) * HDIM + c * 4);
            }
            cp_commit();
        }
    }

    // ---- epilogue: reduce row sums once, normalize, store ----
    #pragma unroll
    for (int h = 0; h < 2; h++) {
        float l = lrow[h];
        l += __shfl_xor_sync(0xffffffffu, l, 1);
        l += __shfl_xor_sync(0xffffffffu, l, 2);
        const float linv = 1.0f / l;
        const int rg = f0 + w * 16 + gid + 8 * h;
        float* op = out + ((size_t)b * SEQ + rg) * HIDDEN + nh * HDIM;
        #pragma unroll
        for (int nb = 0; nb < 8; nb++) {
            float2 v;
            v.x = O[nb][2 * h] * linv;
            v.y = O[nb][2 * h + 1] * linv;
            *(float2*)(op + nb * 8 + 2 * tid4) = v;
        }
    }
}

// ---------------------------------------------------------------------------
// kernel_launch
// ---------------------------------------------------------------------------
extern "C" void kernel_launch(void* const* d_in, const int* in_sizes, int n_in,
                              void* d_out, int out_size)
{
    (void)in_sizes; (void)n_in; (void)out_size;

    const float* from_t = (const float*)d_in[0];
    const float* to_t   = (const float*)d_in[1];
    const int*   msk    = (const int*)d_in[2];
    const float* Wq     = (const float*)d_in[3];
    const float* bq     = (const float*)d_in[4];
    const float* Wk     = (const float*)d_in[5];
    const float* bk     = (const float*)d_in[6];
    const float* Wv     = (const float*)d_in[7];
    const float* bv     = (const float*)d_in[8];
    float* out = (float*)d_out;

    float *qp, *kp, *vp; unsigned* mb;
    cudaGetSymbolAddress((void**)&qp, g_Qs);
    cudaGetSymbolAddress((void**)&kp, g_Ks);
    cudaGetSymbolAddress((void**)&vp, g_Vs);
    cudaGetSymbolAddress((void**)&mb, g_Mbits);

    cudaFuncSetAttribute(gemm_mma_kernel,
                         cudaFuncAttributeMaxDynamicSharedMemorySize, GEMM_SMEM);
    cudaFuncSetAttribute(flash_mma_kernel,
                         cudaFuncAttributeMaxDynamicSharedMemorySize, ATT_SMEM);

    // pack mask to bits (independent of GEMM outputs)
    mask_bits_kernel<<<(MROWS * 32 + 255) / 256, 256>>>(msk, mb);

    dim3 gg(HIDDEN / 128, MROWS / 128, 3);   // (8, 32, 3)
    gemm_mma_kernel<<<gg, 256, GEMM_SMEM>>>(from_t, to_t, Wq, bq, Wk, bk,
                                            Wv, bv, qp, kp, vp);

    dim3 gf(SEQ / 64, BATCH * NHEADS);       // (32, 32) = 1024 CTAs
    flash_mma_kernel<<<gf, 128, ATT_SMEM>>>(qp, kp, vp, mb, out);
}